// round 9
// baseline (speedup 1.0000x reference)
#include <cuda_runtime.h>
#include <cstdint>
#include <math.h>

#define B_    256
#define T_    2048
#define E_    128
#define WIN_  5
#define PAD_  2
#define OC_   128
#define TT    128
#define TILES_PER_CTA 4
#define NQ    4
#define NWARP 8

#define ASTR   136                       // stride in floats; 136 % 32 == 8 -> LDS.64 conflict-free
#define HROWS  132
// smem layout (floats)
#define SA0_F  0
#define SA1_F  (HROWS * ASTR)            // 17952
#define SB_F   (2 * HROWS * ASTR)        // 35904
#define SSC_F  (SB_F + OC_ * ASTR)       // 53312
#define SRED_F (SSC_F + 128)             // 53440
#define SCM_F  (SRED_F + 256)            // 53696
#define SFLAG_F (SCM_F + 128)            // 53824
#define SMEM_FLOATS (SFLAG_F + 4)
#define SMEM_BYTES  (SMEM_FLOATS * 4)    // 215312 B

// k-dim permutation within each 8-group: pairs (k, k+4) become adjacent
#define PERM(e)  ((((e) & 0xF8)) | (((e) & 3) << 1) | ((((e) >> 2) & 1)))
// inverse: stored position p -> logical e
#define IPERM(p) ((((p) & 0xF8)) | ((((p) & 1)) << 2) | ((((p) >> 1) & 3)))

__device__ float gWs[B_ * NQ * OC_];     // per-(b,quarter) channel maxima
__device__ int   gCnt[B_];               // ticket counters (never reset; mod-4)

__device__ __forceinline__ uint32_t smem_u32(const void* p) {
    uint32_t a;
    asm("{ .reg .u64 t; cvta.to.shared.u64 t, %1; cvt.u32.u64 %0, t; }" : "=r"(a) : "l"(p));
    return a;
}
__device__ __forceinline__ float tf32f(float x) {
    uint32_t r;
    asm("cvt.rna.tf32.f32 %0, %1;" : "=r"(r) : "f"(x));
    return __uint_as_float(r);
}
__device__ __forceinline__ void cpa4(uint32_t dst, const float* src, int sz) {
    asm volatile("cp.async.ca.shared.global [%0], [%1], 4, %2;"
                 :: "r"(dst), "l"(src), "r"(sz));
}
#define CP_COMMIT() asm volatile("cp.async.commit_group;" ::: "memory")
#define CP_WAIT0()  asm volatile("cp.async.wait_group 0;" ::: "memory")

__device__ __forceinline__ void mma_tf32(float* c, const uint32_t* a, const uint32_t* b) {
    asm volatile(
        "mma.sync.aligned.m16n8k8.row.col.f32.tf32.tf32.f32 "
        "{%0,%1,%2,%3}, {%4,%5,%6,%7}, {%8,%9}, {%0,%1,%2,%3};"
        : "+f"(c[0]), "+f"(c[1]), "+f"(c[2]), "+f"(c[3])
        : "r"(a[0]), "r"(a[1]), "r"(a[2]), "r"(a[3]), "r"(b[0]), "r"(b[1]));
}

__global__ __launch_bounds__(256, 1)
void fused_kernel(const int* __restrict__ x, const float* __restrict__ emb,
                  const float* __restrict__ attw, const float* __restrict__ attb,
                  const float* __restrict__ cnnw, const float* __restrict__ cnnb,
                  float* __restrict__ out) {
    extern __shared__ float smem[];
    const uint32_t sbase = smem_u32(smem);
    float* sB   = smem + SB_F;
    float* sSc  = smem + SSC_F;
    float* sRed = smem + SRED_F;
    float* sCM  = smem + SCM_F;
    int*   sFlag = (int*)(smem + SFLAG_F);

    const int tid = threadIdx.x;
    const int wid = tid >> 5, lid = tid & 31;
    const int gid = lid >> 2, tig = lid & 3;
    const int wm  = wid >> 2, wn = wid & 3;
    const int q = blockIdx.x, b = blockIdx.y;

    // ---- issue gather of tile 0 (cp.async, permuted dst, zero-fill halo) ----
    {
        const int t0 = q * TILES_PER_CTA * TT;
        const uint32_t buf = sbase + SA0_F * 4;
        for (int r = wid; r < HROWS; r += NWARP) {
            int tg = t0 + r - PAD_;
            int inb = (tg >= 0 && tg < T_);
            int tok = inb ? x[(size_t)b * T_ + tg] : 0;
            const float* src = emb + (size_t)tok * E_;
            uint32_t drow = buf + (uint32_t)(r * ASTR) * 4;
            #pragma unroll
            for (int i = 0; i < 4; i++) {
                int e = lid + 32 * i;
                cpa4(drow + PERM(e) * 4, src + e, inb ? 4 : 0);
            }
        }
        CP_COMMIT();
    }

    // ---- stage B: tf32-round cnn_w into permuted smem (overlaps gather) ----
    for (int i = tid; i < OC_ * E_ / 4; i += 256) {
        int o = i >> 5, e0 = (i & 31) * 4;
        float4 v = *(const float4*)(cnnw + o * E_ + e0);
        float* dr = sB + o * ASTR;
        dr[PERM(e0 + 0)] = tf32f(v.x);
        dr[PERM(e0 + 1)] = tf32f(v.y);
        dr[PERM(e0 + 2)] = tf32f(v.z);
        dr[PERM(e0 + 3)] = tf32f(v.w);
    }
    if (tid < 128) sCM[tid] = -3.4e38f;

    const float ab = __ldg(attb);
    CP_WAIT0();
    __syncthreads();

    for (int tile = 0; tile < TILES_PER_CTA; tile++) {
        float* cur = smem + ((tile & 1) ? SA1_F : SA0_F);

        // ---- prefetch next tile into the other buffer ----
        if (tile < TILES_PER_CTA - 1) {
            const int t0n = (q * TILES_PER_CTA + tile + 1) * TT;
            const uint32_t buf = sbase + ((tile & 1) ? SA0_F : SA1_F) * 4;
            for (int r = wid; r < HROWS; r += NWARP) {
                int tg = t0n + r - PAD_;
                int inb = (tg >= 0 && tg < T_);
                int tok = inb ? x[(size_t)b * T_ + tg] : 0;
                const float* src = emb + (size_t)tok * E_;
                uint32_t drow = buf + (uint32_t)(r * ASTR) * 4;
                #pragma unroll
                for (int i = 0; i < 4; i++) {
                    int e = lid + 32 * i;
                    cpa4(drow + PERM(e) * 4, src + e, inb ? 4 : 0);
                }
            }
            CP_COMMIT();
        }

        // ---- scores (warp per token); read stored pos p, map weight via IPERM ----
        for (int t = wid; t < TT; t += NWARP) {
            float acc = 0.f;
            #pragma unroll
            for (int k = 0; k < WIN_; k++) {
                const float* er = cur + (t + k) * ASTR;
                const float* wr = attw + k * E_;
                #pragma unroll
                for (int m = 0; m < 4; m++) {
                    int p = lid + 32 * m;
                    acc = fmaf(er[p], __ldg(wr + IPERM(p)), acc);
                }
            }
            #pragma unroll
            for (int s = 16; s >= 1; s >>= 1) acc += __shfl_xor_sync(0xffffffffu, acc, s);
            if (lid == 0) sSc[t] = 1.f / (1.f + __expf(-(acc + ab)));
        }
        __syncthreads();

        // ---- GEMM 128x128x128: warp grid 2x4, m16n8k8 tf32, LDS.64 fragments ----
        float c[4][4][4];
        #pragma unroll
        for (int mt = 0; mt < 4; mt++)
            #pragma unroll
            for (int nt = 0; nt < 4; nt++)
                #pragma unroll
                for (int r = 0; r < 4; r++) c[mt][nt][r] = 0.f;

        const float* Ab = cur + (wm * 64 + PAD_ + gid) * ASTR + 2 * tig;
        const float* Bb = sB + (wn * 32 + gid) * ASTR + 2 * tig;

        #pragma unroll
        for (int ks = 0; ks < 16; ks++) {
            const int kc = ks * 8;
            uint32_t a[4][4], bf[4][2];
            #pragma unroll
            for (int mt = 0; mt < 4; mt++) {
                float2 r0 = *(const float2*)(Ab + mt * 16 * ASTR + kc);
                float2 r1 = *(const float2*)(Ab + mt * 16 * ASTR + 8 * ASTR + kc);
                a[mt][0] = __float_as_uint(r0.x);
                a[mt][2] = __float_as_uint(r0.y);
                a[mt][1] = __float_as_uint(r1.x);
                a[mt][3] = __float_as_uint(r1.y);
            }
            #pragma unroll
            for (int nt = 0; nt < 4; nt++) {
                float2 rb = *(const float2*)(Bb + nt * 8 * ASTR + kc);
                bf[nt][0] = __float_as_uint(rb.x);
                bf[nt][1] = __float_as_uint(rb.y);
            }
            #pragma unroll
            for (int mt = 0; mt < 4; mt++)
                #pragma unroll
                for (int nt = 0; nt < 4; nt++)
                    mma_tf32(c[mt][nt], a[mt], bf[nt]);
        }

        // ---- epilogue: gate by score, per-column max ----
        float s0[4], s1[4];
        #pragma unroll
        for (int mt = 0; mt < 4; mt++) {
            s0[mt] = sSc[wm * 64 + mt * 16 + gid];
            s1[mt] = sSc[wm * 64 + mt * 16 + gid + 8];
        }
        #pragma unroll
        for (int nt = 0; nt < 4; nt++) {
            float m0 = -3.4e38f, m1 = -3.4e38f;
            #pragma unroll
            for (int mt = 0; mt < 4; mt++) {
                m0 = fmaxf(m0, fmaxf(c[mt][nt][0] * s0[mt], c[mt][nt][2] * s1[mt]));
                m1 = fmaxf(m1, fmaxf(c[mt][nt][1] * s0[mt], c[mt][nt][3] * s1[mt]));
            }
            #pragma unroll
            for (int off = 4; off < 32; off <<= 1) {
                m0 = fmaxf(m0, __shfl_xor_sync(0xffffffffu, m0, off));
                m1 = fmaxf(m1, __shfl_xor_sync(0xffffffffu, m1, off));
            }
            if (gid == 0) {
                int col = wn * 32 + nt * 8 + tig * 2;
                sRed[wm * 128 + col]     = m0;
                sRed[wm * 128 + col + 1] = m1;
            }
        }
        CP_WAIT0();
        __syncthreads();

        if (tid < 128)
            sCM[tid] = fmaxf(sCM[tid], fmaxf(sRed[tid], sRed[128 + tid]));
        // no barrier needed: sRed next written only after the next __syncthreads()
    }

    __syncthreads();
    if (tid < 128) gWs[((size_t)b * NQ + q) * OC_ + tid] = sCM[tid];
    __threadfence();
    if (tid == 0) {
        int old = atomicAdd(&gCnt[b], 1);
        *sFlag = ((old & 3) == 3);
    }
    __syncthreads();

    // last CTA for this batch reduces the 4 quarters + bias + tanh
    if (*sFlag && tid < 128) {
        __threadfence();
        const volatile float* w = gWs + (size_t)b * NQ * OC_;
        float m = fmaxf(fmaxf(w[tid], w[OC_ + tid]),
                        fmaxf(w[2 * OC_ + tid], w[3 * OC_ + tid]));
        out[(size_t)b * OC_ + tid] = tanhf(m + cnnb[tid]);
    }
}

extern "C" void kernel_launch(void* const* d_in, const int* in_sizes, int n_in,
                              void* d_out, int out_size) {
    const int*   x    = (const int*)d_in[0];
    const float* emb  = (const float*)d_in[1];
    const float* attw = (const float*)d_in[2];
    const float* attb = (const float*)d_in[3];
    const float* cnnw = (const float*)d_in[4];
    const float* cnnb = (const float*)d_in[5];

    (void)cudaFuncSetAttribute(fused_kernel,
                               cudaFuncAttributeMaxDynamicSharedMemorySize, SMEM_BYTES);

    dim3 grid(NQ, B_);
    fused_kernel<<<grid, 256, SMEM_BYTES, 0>>>(x, emb, attw, attb, cnnw, cnnb,
                                               (float*)d_out);
}

// round 11
// speedup vs baseline: 1.2108x; 1.2108x over previous
#include <cuda_runtime.h>
#include <cstdint>
#include <math.h>

#define B_    256
#define T_    2048
#define E_    128
#define WIN_  5
#define PAD_  2
#define OC_   128
#define TT    64                          // tokens per tile (halved -> 2 CTAs/SM)
#define TILES_PER_CTA 4
#define NQ    8                           // token-eighths per batch -> grid.x
#define NWARP 8

#define ASTR   136                        // stride (floats); 136%32==8 -> LDS.64 conflict-free
#define HROWS  (TT + WIN_ - 1)            // 68
// smem layout (floats)
#define SA_F   0                          // [68][136] fp32 embed (PERM k-layout)
#define SB_F   (HROWS * ASTR)             // 9248   [128][136] tf32 cnn_w (PERM)
#define SSC_F  (SB_F + OC_ * ASTR)        // 26656  [64] scores
#define SRED_F (SSC_F + 64)               // 26720  [2][128]
#define SCM_F  (SRED_F + 256)             // 26976  [128]
#define SFLAG_F (SCM_F + 128)             // 27104
#define SMEM_FLOATS (SFLAG_F + 4)
#define SMEM_BYTES  (SMEM_FLOATS * 4)     // 108432 B  (x2 CTAs = 216.9 KB/SM)

// k-dim permutation within each 8-group: logical (k, k+4) stored adjacently
#define PERM(e)  ((((e) & 0xF8)) | (((e) & 3) << 1) | ((((e) >> 2) & 1)))
#define IPERM(p) ((((p) & 0xF8)) | ((((p) & 1)) << 2) | ((((p) >> 1) & 3)))

__device__ float gWs[B_ * NQ * OC_];      // per-(b,eighth) channel maxima
__device__ int   gCnt[B_];                // ticket counters (mod-8, never reset)

__device__ __forceinline__ float tf32f(float x) {
    uint32_t r;
    asm("cvt.rna.tf32.f32 %0, %1;" : "=r"(r) : "f"(x));
    return __uint_as_float(r);
}
__device__ __forceinline__ void mma_tf32(float* c, const uint32_t* a, const uint32_t* b) {
    asm volatile(
        "mma.sync.aligned.m16n8k8.row.col.f32.tf32.tf32.f32 "
        "{%0,%1,%2,%3}, {%4,%5,%6,%7}, {%8,%9}, {%0,%1,%2,%3};"
        : "+f"(c[0]), "+f"(c[1]), "+f"(c[2]), "+f"(c[3])
        : "r"(a[0]), "r"(a[1]), "r"(a[2]), "r"(a[3]), "r"(b[0]), "r"(b[1]));
}

__global__ __launch_bounds__(256, 2)
void fused_kernel(const int* __restrict__ x, const float* __restrict__ emb,
                  const float* __restrict__ attw, const float* __restrict__ attb,
                  const float* __restrict__ cnnw, const float* __restrict__ cnnb,
                  float* __restrict__ out) {
    extern __shared__ float smem[];
    float* sA   = smem + SA_F;
    float* sB   = smem + SB_F;
    float* sSc  = smem + SSC_F;
    float* sRed = smem + SRED_F;
    float* sCM  = smem + SCM_F;
    int*   sFlag = (int*)(smem + SFLAG_F);

    const int tid = threadIdx.x;
    const int wid = tid >> 5, lid = tid & 31;
    const int gid = lid >> 2, tig = lid & 3;
    const int wm  = wid >> 2, wn = wid & 3;   // warp grid 2(M) x 4(N)
    const int q = blockIdx.x, b = blockIdx.y;

    // ---- stage B once per CTA: tf32-round cnn_w into PERM smem layout ----
    for (int i = tid; i < OC_ * E_ / 4; i += 256) {
        int o = i >> 5, e0 = (i & 31) * 4;
        float4 v = *(const float4*)(cnnw + o * E_ + e0);
        float* dr = sB + o * ASTR;
        dr[PERM(e0 + 0)] = tf32f(v.x);
        dr[PERM(e0 + 1)] = tf32f(v.y);
        dr[PERM(e0 + 2)] = tf32f(v.z);
        dr[PERM(e0 + 3)] = tf32f(v.w);
    }
    if (tid < 128) sCM[tid] = -3.4e38f;

    const float ab = __ldg(attb);

    for (int tile = 0; tile < TILES_PER_CTA; tile++) {
        const int t0 = (q * TILES_PER_CTA + tile) * TT;
        __syncthreads();   // prev tile consumed (covers B/CM init on tile 0)

        // ---- gather embed rows (-2 .. TT+1), PERM k-layout ----
        for (int r = wid; r < HROWS; r += NWARP) {
            int tg = t0 + r - PAD_;
            float4 v = make_float4(0.f, 0.f, 0.f, 0.f);
            if (tg >= 0 && tg < T_) {
                int tok = x[(size_t)b * T_ + tg];
                v = *(const float4*)(emb + (size_t)tok * E_ + lid * 4);
            }
            float* dr = sA + r * ASTR;
            int e0 = lid * 4;
            dr[PERM(e0 + 0)] = v.x;
            dr[PERM(e0 + 1)] = v.y;
            dr[PERM(e0 + 2)] = v.z;
            dr[PERM(e0 + 3)] = v.w;
        }
        __syncthreads();

        // ---- sliding-window scores (warp per token; IPERM weight map) ----
        for (int t = wid; t < TT; t += NWARP) {
            float acc = 0.f;
            #pragma unroll
            for (int k = 0; k < WIN_; k++) {
                const float* er = sA + (t + k) * ASTR;
                const float* wr = attw + k * E_;
                #pragma unroll
                for (int m = 0; m < 4; m++) {
                    int p = lid + 32 * m;
                    acc = fmaf(er[p], __ldg(wr + IPERM(p)), acc);
                }
            }
            #pragma unroll
            for (int s = 16; s >= 1; s >>= 1) acc += __shfl_xor_sync(0xffffffffu, acc, s);
            if (lid == 0) sSc[t] = 1.f / (1.f + __expf(-(acc + ab)));
        }
        __syncthreads();

        // ---- GEMM 64x128x128: warp tile 32x32, m16n8k8 tf32, LDS.64 frags ----
        float c[2][4][4];
        #pragma unroll
        for (int mt = 0; mt < 2; mt++)
            #pragma unroll
            for (int nt = 0; nt < 4; nt++)
                #pragma unroll
                for (int r = 0; r < 4; r++) c[mt][nt][r] = 0.f;

        const float* Ab = sA + (wm * 32 + PAD_ + gid) * ASTR + 2 * tig;
        const float* Bb = sB + (wn * 32 + gid) * ASTR + 2 * tig;

        #pragma unroll
        for (int ks = 0; ks < 16; ks++) {
            const int kc = ks * 8;
            uint32_t a[2][4], bf[4][2];
            #pragma unroll
            for (int mt = 0; mt < 2; mt++) {
                float2 r0 = *(const float2*)(Ab + mt * 16 * ASTR + kc);
                float2 r1 = *(const float2*)(Ab + mt * 16 * ASTR + 8 * ASTR + kc);
                a[mt][0] = __float_as_uint(r0.x);
                a[mt][2] = __float_as_uint(r0.y);
                a[mt][1] = __float_as_uint(r1.x);
                a[mt][3] = __float_as_uint(r1.y);
            }
            #pragma unroll
            for (int nt = 0; nt < 4; nt++) {
                float2 rb = *(const float2*)(Bb + nt * 8 * ASTR + kc);
                bf[nt][0] = __float_as_uint(rb.x);
                bf[nt][1] = __float_as_uint(rb.y);
            }
            #pragma unroll
            for (int mt = 0; mt < 2; mt++)
                #pragma unroll
                for (int nt = 0; nt < 4; nt++)
                    mma_tf32(c[mt][nt], a[mt], bf[nt]);
        }

        // ---- epilogue: gate by score, per-column max ----
        float s0[2], s1[2];
        #pragma unroll
        for (int mt = 0; mt < 2; mt++) {
            s0[mt] = sSc[wm * 32 + mt * 16 + gid];
            s1[mt] = sSc[wm * 32 + mt * 16 + gid + 8];
        }
        #pragma unroll
        for (int nt = 0; nt < 4; nt++) {
            float m0 = -3.4e38f, m1 = -3.4e38f;
            #pragma unroll
            for (int mt = 0; mt < 2; mt++) {
                m0 = fmaxf(m0, fmaxf(c[mt][nt][0] * s0[mt], c[mt][nt][2] * s1[mt]));
                m1 = fmaxf(m1, fmaxf(c[mt][nt][1] * s0[mt], c[mt][nt][3] * s1[mt]));
            }
            #pragma unroll
            for (int off = 4; off < 32; off <<= 1) {
                m0 = fmaxf(m0, __shfl_xor_sync(0xffffffffu, m0, off));
                m1 = fmaxf(m1, __shfl_xor_sync(0xffffffffu, m1, off));
            }
            if (gid == 0) {
                int col = wn * 32 + nt * 8 + tig * 2;
                sRed[wm * 128 + col]     = m0;
                sRed[wm * 128 + col + 1] = m1;
            }
        }
        __syncthreads();

        if (tid < 128)
            sCM[tid] = fmaxf(sCM[tid], fmaxf(sRed[tid], sRed[128 + tid]));
        // next write to sRed happens only after the next __syncthreads()
    }

    __syncthreads();
    if (tid < 128) gWs[((size_t)b * NQ + q) * OC_ + tid] = sCM[tid];
    __threadfence();
    if (tid == 0) {
        int old = atomicAdd(&gCnt[b], 1);
        *sFlag = ((old & 7) == 7);
    }
    __syncthreads();

    // last CTA for this batch: reduce 8 eighths + bias + tanh
    if (*sFlag && tid < 128) {
        __threadfence();
        const volatile float* w = gWs + (size_t)b * NQ * OC_;
        float m = w[tid];
        #pragma unroll
        for (int s = 1; s < NQ; s++) m = fmaxf(m, w[s * OC_ + tid]);
        out[(size_t)b * OC_ + tid] = tanhf(m + cnnb[tid]);
    }
}

extern "C" void kernel_launch(void* const* d_in, const int* in_sizes, int n_in,
                              void* d_out, int out_size) {
    const int*   x    = (const int*)d_in[0];
    const float* emb  = (const float*)d_in[1];
    const float* attw = (const float*)d_in[2];
    const float* attb = (const float*)d_in[3];
    const float* cnnw = (const float*)d_in[4];
    const float* cnnb = (const float*)d_in[5];

    (void)cudaFuncSetAttribute(fused_kernel,
                               cudaFuncAttributeMaxDynamicSharedMemorySize, SMEM_BYTES);

    dim3 grid(NQ, B_);
    fused_kernel<<<grid, 256, SMEM_BYTES, 0>>>(x, emb, attw, attb, cnnw, cnnb,
                                               (float*)d_out);
}

// round 15
// speedup vs baseline: 1.5425x; 1.2740x over previous
#include <cuda_runtime.h>
#include <cstdint>
#include <math.h>

#define B_    256
#define T_    2048
#define E_    128
#define WIN_  5
#define PAD_  2
#define OC_   128
#define TT    64                          // tokens per tile (2 CTAs/SM)
#define TILES_PER_CTA 4
#define NQ    8                           // token-eighths per batch -> grid.x
#define NWARP 8

#define ASTR   136                        // stride (floats); 136%32==8 -> LDS.64 conflict-free
#define HROWS  (TT + WIN_ - 1)            // 68
// smem layout (floats)
#define SA_F   0                          // [68][136] fp32 embed (PERM k-layout)
#define SB_F   (HROWS * ASTR)             // 9248   [128][136] tf32 cnn_w (PERM)
#define SSC_F  (SB_F + OC_ * ASTR)        // 26656  [64] scores
#define SRED_F (SSC_F + 64)               // 26720  [2][128]
#define SCM_F  (SRED_F + 256)             // 26976  [128]
#define SFLAG_F (SCM_F + 128)             // 27104
#define SMEM_FLOATS (SFLAG_F + 4)
#define SMEM_BYTES  (SMEM_FLOATS * 4)     // 108432 B  (x2 CTAs = 216.9 KB/SM)

// k-dim permutation within each 8-group: logical (k, k+4) stored adjacently
#define PERM(e)  ((((e) & 0xF8)) | (((e) & 3) << 1) | ((((e) >> 2) & 1)))
#define IPERM(p) ((((p) & 0xF8)) | ((((p) & 1)) << 2) | ((((p) >> 1) & 3)))

__device__ float gWs[B_ * NQ * OC_];      // per-(b,eighth) channel maxima
__device__ int   gCnt[B_];                // ticket counters (mod-8, never reset)

__device__ __forceinline__ float tf32f(float x) {
    uint32_t r;
    asm("cvt.rna.tf32.f32 %0, %1;" : "=r"(r) : "f"(x));
    return __uint_as_float(r);
}
__device__ __forceinline__ void mma_tf32(float* c, const uint32_t* a, const uint32_t* b) {
    asm volatile(
        "mma.sync.aligned.m16n8k8.row.col.f32.tf32.tf32.f32 "
        "{%0,%1,%2,%3}, {%4,%5,%6,%7}, {%8,%9}, {%0,%1,%2,%3};"
        : "+f"(c[0]), "+f"(c[1]), "+f"(c[2]), "+f"(c[3])
        : "r"(a[0]), "r"(a[1]), "r"(a[2]), "r"(a[3]), "r"(b[0]), "r"(b[1]));
}

__global__ __launch_bounds__(256, 2)
void fused_kernel(const int* __restrict__ x, const float* __restrict__ emb,
                  const float* __restrict__ attw, const float* __restrict__ attb,
                  const float* __restrict__ cnnw, const float* __restrict__ cnnb,
                  float* __restrict__ out) {
    extern __shared__ float smem[];
    float* sA   = smem + SA_F;
    float* sB   = smem + SB_F;
    float* sSc  = smem + SSC_F;
    float* sRed = smem + SRED_F;
    float* sCM  = smem + SCM_F;
    int*   sFlag = (int*)(smem + SFLAG_F);

    const int tid = threadIdx.x;
    const int wid = tid >> 5, lid = tid & 31;
    const int gid = lid >> 2, tig = lid & 3;
    const int wm  = wid >> 2, wn = wid & 3;   // warp grid 2(M) x 4(N)
    const int q = blockIdx.x, b = blockIdx.y;

    // ---- stage B once per CTA: tf32-round cnn_w into PERM smem layout ----
    for (int i = tid; i < OC_ * E_ / 4; i += 256) {
        int o = i >> 5, e0 = (i & 31) * 4;
        float4 v = *(const float4*)(cnnw + o * E_ + e0);
        float* dr = sB + o * ASTR;
        dr[PERM(e0 + 0)] = tf32f(v.x);
        dr[PERM(e0 + 1)] = tf32f(v.y);
        dr[PERM(e0 + 2)] = tf32f(v.z);
        dr[PERM(e0 + 3)] = tf32f(v.w);
    }
    if (tid < 128) sCM[tid] = -3.4e38f;

    // ---- preload attention weights at this lane's 4 stored positions ----
    float wreg[WIN_][4];
    #pragma unroll
    for (int k = 0; k < WIN_; k++)
        #pragma unroll
        for (int m = 0; m < 4; m++)
            wreg[k][m] = __ldg(attw + k * E_ + IPERM(lid + 32 * m));
    const float ab = __ldg(attb);

    for (int tile = 0; tile < TILES_PER_CTA; tile++) {
        const int t0 = (q * TILES_PER_CTA + tile) * TT;
        __syncthreads();   // prev tile consumed (covers B/CM init on tile 0)

        // ---- gather embed rows (-2 .. TT+1), PERM k-layout ----
        for (int r = wid; r < HROWS; r += NWARP) {
            int tg = t0 + r - PAD_;
            float4 v = make_float4(0.f, 0.f, 0.f, 0.f);
            if (tg >= 0 && tg < T_) {
                int tok = x[(size_t)b * T_ + tg];
                v = *(const float4*)(emb + (size_t)tok * E_ + lid * 4);
            }
            float* dr = sA + r * ASTR;
            int e0 = lid * 4;
            dr[PERM(e0 + 0)] = v.x;
            dr[PERM(e0 + 1)] = v.y;
            dr[PERM(e0 + 2)] = v.z;
            dr[PERM(e0 + 3)] = v.w;
        }
        __syncthreads();

        // ---- scores: warp owns tokens [wid*8, wid*8+8), 2 chunks of 4 ----
        // Each chunk loads its 8 covering rows ONCE into registers.
        #pragma unroll
        for (int cch = 0; cch < 2; cch++) {
            const int tb = wid * 8 + cch * 4;     // first token of chunk
            float rv[8][4];
            #pragma unroll
            for (int r = 0; r < 8; r++) {
                const float* er = sA + (tb + r) * ASTR;
                #pragma unroll
                for (int m = 0; m < 4; m++) rv[r][m] = er[lid + 32 * m];
            }
            #pragma unroll
            for (int t = 0; t < 4; t++) {
                float acc = 0.f;
                #pragma unroll
                for (int k = 0; k < WIN_; k++)
                    #pragma unroll
                    for (int m = 0; m < 4; m++)
                        acc = fmaf(rv[t + k][m], wreg[k][m], acc);
                #pragma unroll
                for (int s = 16; s >= 1; s >>= 1)
                    acc += __shfl_xor_sync(0xffffffffu, acc, s);
                if (lid == 0) sSc[tb + t] = 1.f / (1.f + __expf(-(acc + ab)));
            }
        }
        __syncthreads();

        // ---- GEMM 64x128x128: warp tile 32x32, m16n8k8 tf32, LDS.64 frags ----
        float c[2][4][4];
        #pragma unroll
        for (int mt = 0; mt < 2; mt++)
            #pragma unroll
            for (int nt = 0; nt < 4; nt++)
                #pragma unroll
                for (int r = 0; r < 4; r++) c[mt][nt][r] = 0.f;

        const float* Ab = sA + (wm * 32 + PAD_ + gid) * ASTR + 2 * tig;
        const float* Bb = sB + (wn * 32 + gid) * ASTR + 2 * tig;

        #pragma unroll
        for (int ks = 0; ks < 16; ks++) {
            const int kc = ks * 8;
            uint32_t a[2][4], bf[4][2];
            #pragma unroll
            for (int mt = 0; mt < 2; mt++) {
                float2 r0 = *(const float2*)(Ab + mt * 16 * ASTR + kc);
                float2 r1 = *(const float2*)(Ab + mt * 16 * ASTR + 8 * ASTR + kc);
                a[mt][0] = __float_as_uint(r0.x);
                a[mt][2] = __float_as_uint(r0.y);
                a[mt][1] = __float_as_uint(r1.x);
                a[mt][3] = __float_as_uint(r1.y);
            }
            #pragma unroll
            for (int nt = 0; nt < 4; nt++) {
                float2 rb = *(const float2*)(Bb + nt * 8 * ASTR + kc);
                bf[nt][0] = __float_as_uint(rb.x);
                bf[nt][1] = __float_as_uint(rb.y);
            }
            #pragma unroll
            for (int mt = 0; mt < 2; mt++)
                #pragma unroll
                for (int nt = 0; nt < 4; nt++)
                    mma_tf32(c[mt][nt], a[mt], bf[nt]);
        }

        // ---- epilogue: gate by score, per-column max ----
        float s0[2], s1[2];
        #pragma unroll
        for (int mt = 0; mt < 2; mt++) {
            s0[mt] = sSc[wm * 32 + mt * 16 + gid];
            s1[mt] = sSc[wm * 32 + mt * 16 + gid + 8];
        }
        #pragma unroll
        for (int nt = 0; nt < 4; nt++) {
            float m0 = -3.4e38f, m1 = -3.4e38f;
            #pragma unroll
            for (int mt = 0; mt < 2; mt++) {
                m0 = fmaxf(m0, fmaxf(c[mt][nt][0] * s0[mt], c[mt][nt][2] * s1[mt]));
                m1 = fmaxf(m1, fmaxf(c[mt][nt][1] * s0[mt], c[mt][nt][3] * s1[mt]));
            }
            #pragma unroll
            for (int off = 4; off < 32; off <<= 1) {
                m0 = fmaxf(m0, __shfl_xor_sync(0xffffffffu, m0, off));
                m1 = fmaxf(m1, __shfl_xor_sync(0xffffffffu, m1, off));
            }
            if (gid == 0) {
                int col = wn * 32 + nt * 8 + tig * 2;
                sRed[wm * 128 + col]     = m0;
                sRed[wm * 128 + col + 1] = m1;
            }
        }
        __syncthreads();

        if (tid < 128)
            sCM[tid] = fmaxf(sCM[tid], fmaxf(sRed[tid], sRed[128 + tid]));
        // next write to sRed happens only after the next __syncthreads()
    }

    __syncthreads();
    if (tid < 128) gWs[((size_t)b * NQ + q) * OC_ + tid] = sCM[tid];
    __threadfence();
    if (tid == 0) {
        int old = atomicAdd(&gCnt[b], 1);
        *sFlag = ((old & 7) == 7);
    }
    __syncthreads();

    // last CTA for this batch: reduce 8 eighths + bias + tanh
    if (*sFlag && tid < 128) {
        __threadfence();
        const volatile float* w = gWs + (size_t)b * NQ * OC_;
        float m = w[tid];
        #pragma unroll
        for (int s = 1; s < NQ; s++) m = fmaxf(m, w[s * OC_ + tid]);
        out[(size_t)b * OC_ + tid] = tanhf(m + cnnb[tid]);
    }
}

extern "C" void kernel_launch(void* const* d_in, const int* in_sizes, int n_in,
                              void* d_out, int out_size) {
    const int*   x    = (const int*)d_in[0];
    const float* emb  = (const float*)d_in[1];
    const float* attw = (const float*)d_in[2];
    const float* attb = (const float*)d_in[3];
    const float* cnnw = (const float*)d_in[4];
    const float* cnnb = (const float*)d_in[5];

    (void)cudaFuncSetAttribute(fused_kernel,
                               cudaFuncAttributeMaxDynamicSharedMemorySize, SMEM_BYTES);

    dim3 grid(NQ, B_);
    fused_kernel<<<grid, 256, SMEM_BYTES, 0>>>(x, emb, attw, attb, cnnw, cnnb,
                                               (float*)d_out);
}